// round 8
// baseline (speedup 1.0000x reference)
#include <cuda_runtime.h>
#include <math.h>

#define BSZ       512
#define NODES     1000
#define HALF      500
#define DIM       128
#define NB_HEADS  8
#define EMB3      384          // DIM * 3 layers, row stride of K_att / V_att
#define HSTR      501          // smem stride for half-node arrays

// Global scratch, double-buffered by layer: layer l reads buf l-1, writes buf l.
__device__ float g_partV[2][BSZ][2][DIM];       // unnormalized sum_n e*V
__device__ float g_esum[2][BSZ][2][NB_HEADS];   // sum_n e per head
__device__ float g_denom[BSZ][2];               // final-layer denominators

// ---------------------------------------------------------------------------
// Mask: runtime layout detection (uint8 / int32 / float32), then decode the
// half-row [base, base+HALF) for batch b into smask.
// ---------------------------------------------------------------------------
__device__ __forceinline__ void load_mask_half(const void* mask, int b, int base,
                                               int tid, unsigned char* smask)
{
    const unsigned char* p = (const unsigned char*)mask;
    bool viol_i32 = false, viol_f32 = false;
    {
        unsigned char b0 = p[4 * tid + 0];
        unsigned char b1 = p[4 * tid + 1];
        unsigned char b2 = p[4 * tid + 2];
        unsigned char b3 = p[4 * tid + 3];
        viol_i32 = (b1 | b2 | b3) != 0;
        bool zero = (b0 | b1 | b2 | b3) == 0;
        bool one  = (b0 == 0 && b1 == 0 && b2 == 0x80 && b3 == 0x3f);
        viol_f32 = !(zero || one);
    }
    const int any_i32_viol = __syncthreads_or(viol_i32);
    const int any_f32_viol = __syncthreads_or(viol_f32);

    if (!any_i32_viol) {
        const int* mi = (const int*)mask + (size_t)b * NODES + base;
        for (int n = tid; n < HALF; n += 256) smask[n] = (mi[n] != 0);
    } else if (!any_f32_viol) {
        const float* mf = (const float*)mask + (size_t)b * NODES + base;
        for (int n = tid; n < HALF; n += 256) smask[n] = (mf[n] != 0.0f);
    } else {
        const unsigned char* mu = (const unsigned char*)mask + (size_t)b * NODES + base;
        for (int n = tid; n < HALF; n += 256) smask[n] = (mu[n] != 0);
    }
    __syncthreads();
}

// Combine partials from scratch buffer `src` into scomb (normalized attention
// output for batch b).
__device__ __forceinline__ void combine_partials(int src, int b, int tid,
                                                 float* scomb)
{
    if (tid < DIM) {
        const int h = tid >> 4;
        const float inv = 1.0f / (g_esum[src][b][0][h] + g_esum[src][b][1][h]);
        scomb[tid] = (g_partV[src][b][0][tid] + g_partV[src][b][1][tid]) * inv;
    }
    __syncthreads();
}

// dst = src_vec @ Ww^T + Wb   (128x128), one thread per output element.
__device__ __forceinline__ void linear128(int tid,
                                          const float* __restrict__ Ww,
                                          const float* __restrict__ Wb,
                                          const float* src_vec, float* dst)
{
    if (tid < DIM) {
        float r = Wb[tid];
        const float* Wr = Ww + tid * DIM;
        #pragma unroll 8
        for (int k = 0; k < DIM; k++) r += __ldg(Wr + k) * src_vec[k];
        dst[tid] = r;
    }
    __syncthreads();
}

// ---------------------------------------------------------------------------
// Layers 0 / 1, half-row granularity: grid = 1024 (b = bid>>1, half = bid&1),
// 256 threads = 8 warps, 8 blocks/SM. Layer 1 first applies W0 to the
// combined layer-0 output. Streams K half (exp weights, no max pass), then
// V half; writes unnormalized partials to scratch buffer `layer`.
// ---------------------------------------------------------------------------
__global__ __launch_bounds__(256, 8)
void attn_partial(const float* __restrict__ K_att,
                  const float* __restrict__ V_att,
                  const void*  __restrict__ mask,
                  const float* __restrict__ query0,
                  const float* __restrict__ W0w,
                  const float* __restrict__ W0b,
                  int layer)
{
    __shared__ __align__(16) float sq[DIM];
    __shared__ float slog[NB_HEADS * HSTR];        // e weights (16 KB)
    __shared__ float ssum[8][NB_HEADS];
    __shared__ __align__(16) float spart[8][DIM];  // per-warp e*V partials (4 KB)
    __shared__ float scomb[DIM];
    __shared__ unsigned char smask[HALF];

    const int bid  = blockIdx.x;
    const int b    = bid >> 1;
    const int half = bid & 1;
    const int base = half * HALF;
    const int tid  = threadIdx.x;
    const int lane = tid & 31;
    const int warp = tid >> 5;

    load_mask_half(mask, b, base, tid, smask);

    if (layer == 0) {
        if (tid < DIM) sq[tid] = query0[b * DIM + tid];
        __syncthreads();
    } else {
        combine_partials(0, b, tid, scomb);
        linear128(tid, W0w, W0b, scomb, sq);    // query after layer 0
    }

    const float4 q4 = reinterpret_cast<const float4*>(sq)[lane];
    const float* Kb = K_att + (size_t)b * NODES * EMB3 + (size_t)base * EMB3 + layer * DIM;
    const float* Vb = V_att + (size_t)b * NODES * EMB3 + (size_t)base * EMB3 + layer * DIM;

    // ---- Phase A: K stream -> e weights + per-head partial denominators ---
    {
        float es = 0.f;                 // valid on lanes with (lane&3)==0
        for (int n0 = warp * 4; n0 + 3 < HALF; n0 += 32) {
            float4 k[4];
            #pragma unroll
            for (int i = 0; i < 4; i++)
                k[i] = __ldcs(reinterpret_cast<const float4*>(Kb + (size_t)(n0 + i) * EMB3) + lane);
            #pragma unroll
            for (int i = 0; i < 4; i++) {
                float p = k[i].x * q4.x + k[i].y * q4.y + k[i].z * q4.z + k[i].w * q4.w;
                p += __shfl_xor_sync(0xffffffffu, p, 1);
                p += __shfl_xor_sync(0xffffffffu, p, 2);
                if ((lane & 3) == 0) {
                    const int n = n0 + i;
                    float e = smask[n] ? 0.f : __expf(p * 0.25f);   // 1/sqrt(16)
                    slog[(lane >> 2) * HSTR + n] = e;
                    es += e;
                }
            }
        }
        if ((lane & 3) == 0) ssum[warp][lane >> 2] = es;
    }
    __syncthreads();

    // ---- Phase B: V stream, warp-per-node, 4 loads in flight ---------------
    {
        const float* Lh = slog + (lane >> 2) * HSTR;
        float4 acc = make_float4(0.f, 0.f, 0.f, 0.f);
        int n = warp;
        for (; n + 24 < HALF; n += 32) {
            float4 v[4];
            #pragma unroll
            for (int i = 0; i < 4; i++)
                v[i] = __ldcs(reinterpret_cast<const float4*>(Vb + (size_t)(n + 8 * i) * EMB3) + lane);
            #pragma unroll
            for (int i = 0; i < 4; i++) {
                const float w = Lh[n + 8 * i];
                acc.x += w * v[i].x; acc.y += w * v[i].y;
                acc.z += w * v[i].z; acc.w += w * v[i].w;
            }
        }
        for (; n < HALF; n += 8) {
            float4 v0 = __ldcs(reinterpret_cast<const float4*>(Vb + (size_t)n * EMB3) + lane);
            const float w = Lh[n];
            acc.x += w * v0.x; acc.y += w * v0.y; acc.z += w * v0.z; acc.w += w * v0.w;
        }
        reinterpret_cast<float4*>(spart[warp])[lane] = acc;
    }
    __syncthreads();

    if (tid < DIM) {
        float r = 0.f;
        #pragma unroll
        for (int w = 0; w < 8; w++) r += spart[w][tid];
        g_partV[layer][b][half][tid] = r;
    }
    if (tid >= DIM && tid < DIM + NB_HEADS) {
        const int h = tid - DIM;
        float s = 0.f;
        #pragma unroll
        for (int w = 0; w < 8; w++) s += ssum[w][h];
        g_esum[layer][b][half][h] = s;
    }
}

// ---------------------------------------------------------------------------
// Final layer, half-row granularity: combine layer-1 partials (buffer 1),
// apply W0 (the post-layer-1 linear!) THEN Wq, single-head logits with
// 10*tanh clip, write UNNORMALIZED exp to out and per-half denominator.
// ---------------------------------------------------------------------------
__global__ __launch_bounds__(256, 8)
void attn_final_partial(const float* __restrict__ K_att,
                        const void*  __restrict__ mask,
                        const float* __restrict__ W0w,
                        const float* __restrict__ W0b,
                        const float* __restrict__ Wqw,
                        const float* __restrict__ Wqb,
                        float* __restrict__ out)
{
    __shared__ __align__(16) float sq[DIM];
    __shared__ __align__(16) float sq1[DIM];
    __shared__ float spartl[NB_HEADS * HSTR];   // per-16-dim-group dot partials (16 KB)
    __shared__ float scomb[DIM];
    __shared__ float sreds[8];
    __shared__ unsigned char smask[HALF];

    const int bid  = blockIdx.x;
    const int b    = bid >> 1;
    const int half = bid & 1;
    const int base = half * HALF;
    const int tid  = threadIdx.x;
    const int lane = tid & 31;
    const int warp = tid >> 5;

    load_mask_half(mask, b, base, tid, smask);
    combine_partials(1, b, tid, scomb);
    linear128(tid, W0w, W0b, scomb, sq1);   // query = out1 @ W0^T + W0b
    linear128(tid, Wqw, Wqb, sq1, sq);      // q_final = query @ Wq^T + Wqb

    const float4 q4 = reinterpret_cast<const float4*>(sq)[lane];
    const float* Kb = K_att + (size_t)b * NODES * EMB3 + (size_t)base * EMB3 + 2 * DIM;

    for (int n0 = warp * 4; n0 + 3 < HALF; n0 += 32) {
        float4 k[4];
        #pragma unroll
        for (int i = 0; i < 4; i++)
            k[i] = __ldcs(reinterpret_cast<const float4*>(Kb + (size_t)(n0 + i) * EMB3) + lane);
        #pragma unroll
        for (int i = 0; i < 4; i++) {
            float p = k[i].x * q4.x + k[i].y * q4.y + k[i].z * q4.z + k[i].w * q4.w;
            p += __shfl_xor_sync(0xffffffffu, p, 1);
            p += __shfl_xor_sync(0xffffffffu, p, 2);
            if ((lane & 3) == 0) spartl[(lane >> 2) * HSTR + (n0 + i)] = p;
        }
    }
    __syncthreads();

    // Combine partials -> exp(clip(logit)); |logit| <= 10 so no max pass.
    const float scale = 0.0883883476483184f;   // 1/sqrt(128)
    float s = 0.f;
    float* ob = out + (size_t)b * NODES + base;
    for (int n = tid; n < HALF; n += 256) {
        float d = 0.f;
        #pragma unroll
        for (int h = 0; h < NB_HEADS; h++) d += spartl[h * HSTR + n];
        float e = smask[n] ? 0.f : __expf(10.0f * tanhf(d * scale));
        ob[n] = e;
        s += e;
    }
    #pragma unroll
    for (int o = 16; o; o >>= 1) s += __shfl_xor_sync(0xffffffffu, s, o);
    if (lane == 0) sreds[warp] = s;
    __syncthreads();
    if (tid < 32) {
        float ss = (lane < 8) ? sreds[lane] : 0.f;
        #pragma unroll
        for (int o = 4; o; o >>= 1) ss += __shfl_xor_sync(0xffffffffu, ss, o);
        if (lane == 0) g_denom[b][half] = ss;
    }
}

// ---------------------------------------------------------------------------
// Normalize: out[b][n] /= (denom[b][0] + denom[b][1])
// ---------------------------------------------------------------------------
__global__ __launch_bounds__(256)
void normalize_out(float* __restrict__ out)
{
    const int b   = blockIdx.x;
    const int tid = threadIdx.x;
    const float inv = 1.0f / (g_denom[b][0] + g_denom[b][1]);
    float* ob = out + (size_t)b * NODES;
    for (int n = tid; n < NODES; n += 256) ob[n] *= inv;
}

// ---------------------------------------------------------------------------
extern "C" void kernel_launch(void* const* d_in, const int* in_sizes, int n_in,
                              void* d_out, int out_size)
{
    const float* query = (const float*)d_in[0];
    const float* K_att = (const float*)d_in[1];
    const float* V_att = (const float*)d_in[2];
    const void*  mask  = d_in[3];
    const float* W0w   = (const float*)d_in[4];
    const float* W0b   = (const float*)d_in[5];
    const float* Wqw   = (const float*)d_in[6];
    const float* Wqb   = (const float*)d_in[7];
    float* out = (float*)d_out;

    attn_partial      <<<2 * BSZ, 256>>>(K_att, V_att, mask, query, W0w, W0b, 0);
    attn_partial      <<<2 * BSZ, 256>>>(K_att, V_att, mask, query, W0w, W0b, 1);
    attn_final_partial<<<2 * BSZ, 256>>>(K_att, mask, W0w, W0b, Wqw, Wqb, out);
    normalize_out     <<<BSZ, 256>>>(out);
}